// round 10
// baseline (speedup 1.0000x reference)
#include <cuda_runtime.h>
#include <cuda_fp16.h>
#include <math.h>
#include <stdint.h>

// Problem constants (fixed by the dataset)
#define NN 100000   // nodes
#define DD 128      // feature dim (= hidden dim)
#define EE 1600000  // edges
#define SCAN_BLOCKS 98   // ceil(NN/1024)

// ---------------- scratch (static device globals; no allocation) ----------------
__device__ __align__(16) float g_agg[NN * DD];
__device__ __align__(16) float g_x1[NN * DD];
__device__ __align__(16) float g_x2[NN * DD];
__device__ __align__(16) __half g_h[NN * DD];   // fp16 copy of gather source
__device__ int   g_deg[NN];
__device__ int   g_off[NN + 1];
__device__ int   g_cursor[NN];
__device__ int   g_csr[EE];
__device__ int   g_part[128];
__device__ float g_bnsum[2 * DD];
__device__ float g_bnsq[2 * DD];
__device__ __align__(16) float g_scale[DD];
__device__ __align__(16) float g_shift[DD];
__device__ float g_p1[NN];
__device__ float g_p2[NN];

// ---------------- init: zero deg + BN accumulators ----------------
__global__ void init_kernel() {
    int i = blockIdx.x * blockDim.x + threadIdx.x;
    if (i < NN) g_deg[i] = 0;
    if (i < 2 * DD) { g_bnsum[i] = 0.f; g_bnsq[i] = 0.f; }
}

// ---------------- degree histogram ----------------
__global__ void hist_kernel(const int* __restrict__ dst, int E) {
    int i = blockIdx.x * blockDim.x + threadIdx.x;
    if (i < E) atomicAdd(&g_deg[__ldg(&dst[i])], 1);
}

// ---------------- parallel scan, phase 1: per-chunk sums ----------------
__global__ void scan1_kernel() {
    __shared__ int warp_sums[32];
    int t = threadIdx.x;
    int i = blockIdx.x * 1024 + t;
    int v = (i < NN) ? g_deg[i] : 0;
#pragma unroll
    for (int m = 16; m; m >>= 1) v += __shfl_xor_sync(0xffffffffu, v, m);
    if ((t & 31) == 0) warp_sums[t >> 5] = v;
    __syncthreads();
    if (t < 32) {
        int s = warp_sums[t];
#pragma unroll
        for (int m = 16; m; m >>= 1) s += __shfl_xor_sync(0xffffffffu, s, m);
        if (t == 0) g_part[blockIdx.x] = s;
    }
}

// ---------------- parallel scan, phase 2: scan the 98 partials ----------------
__global__ void scan2_kernel() {
    __shared__ int sm2[128];
    int t = threadIdx.x;
    int v = (t < SCAN_BLOCKS) ? g_part[t] : 0;
    sm2[t] = v;
    __syncthreads();
    for (int d = 1; d < 128; d <<= 1) {
        int y = (t >= d) ? sm2[t - d] : 0;
        __syncthreads();
        sm2[t] += y;
        __syncthreads();
    }
    if (t < SCAN_BLOCKS) g_part[t] = sm2[t] - v;       // exclusive prefix
    if (t == SCAN_BLOCKS - 1) g_off[NN] = sm2[t];      // total = E
}

// ---------------- parallel scan, phase 3: block exclusive scan + base ----------------
__global__ void scan3_kernel() {
    __shared__ int warp_sums[32];
    int t = threadIdx.x;
    int lane = t & 31, wid = t >> 5;
    int i = blockIdx.x * 1024 + t;
    int v = (i < NN) ? g_deg[i] : 0;
    int x = v;
#pragma unroll
    for (int d = 1; d < 32; d <<= 1) {
        int y = __shfl_up_sync(0xffffffffu, x, d);
        if (lane >= d) x += y;
    }
    if (lane == 31) warp_sums[wid] = x;
    __syncthreads();
    if (wid == 0) {
        int s = warp_sums[lane];
#pragma unroll
        for (int d = 1; d < 32; d <<= 1) {
            int y = __shfl_up_sync(0xffffffffu, s, d);
            if (lane >= d) s += y;
        }
        warp_sums[lane] = s;   // inclusive warp-total scan
    }
    __syncthreads();
    int base = g_part[blockIdx.x] + (wid ? warp_sums[wid - 1] : 0);
    int excl = base + x - v;
    if (i < NN) { g_off[i] = excl; g_cursor[i] = excl; }
}

// ---------------- fill CSR: csr[slot] = src, keyed by dst ----------------
__global__ void fill_kernel(const int* __restrict__ src,
                            const int* __restrict__ dst, int E) {
    int i = blockIdx.x * blockDim.x + threadIdx.x;
    if (i >= E) return;
    int d = __ldg(&dst[i]);
    int slot = atomicAdd(&g_cursor[d], 1);
    g_csr[slot] = __ldg(&src[i]);
}

// ---------------- convert to fp16 (optionally fused BN+ReLU) ----------------
template <bool BN>
__global__ void tohalf_kernel(const float* __restrict__ x, int total4) {
    int i = blockIdx.x * blockDim.x + threadIdx.x;
    if (i >= total4) return;
    float4 v = __ldg(&((const float4*)x)[i]);
    if (BN) {
        int c4 = i & 31;
        float4 sc = ((const float4*)g_scale)[c4];
        float4 sh = ((const float4*)g_shift)[c4];
        v.x = fmaxf(fmaf(v.x, sc.x, sh.x), 0.f);
        v.y = fmaxf(fmaf(v.y, sc.y, sh.y), 0.f);
        v.z = fmaxf(fmaf(v.z, sc.z, sh.z), 0.f);
        v.w = fmaxf(fmaf(v.w, sc.w, sh.w), 0.f);
    }
    uint2 o;
    half2 h01 = __floats2half2_rn(v.x, v.y);
    half2 h23 = __floats2half2_rn(v.z, v.w);
    o.x = *(uint32_t*)&h01;
    o.y = *(uint32_t*)&h23;
    ((uint2*)g_h)[i] = o;
}

// ---------------- pull aggregation from fp16 rows ----------------
__global__ void aggregate_kernel() {
    int n = (blockIdx.x * blockDim.x + threadIdx.x) >> 5;
    int lane = threadIdx.x & 31;
    if (n >= NN) return;
    int beg = __ldg(&g_off[n]);
    int end = __ldg(&g_off[n + 1]);
    const uint2* h2 = (const uint2*)g_h;   // 4 halves per uint2; row = 32 uint2

    float4 acc0 = make_float4(0.f, 0.f, 0.f, 0.f);
    float4 acc1 = make_float4(0.f, 0.f, 0.f, 0.f);

    for (int cbase = beg; cbase < end; cbase += 32) {
        int m = min(32, end - cbase);
        int idx = (lane < m) ? __ldg(&g_csr[cbase + lane]) : 0;
        int j = 0;
        for (; j + 8 <= m; j += 8) {
            uint2 v[8];
#pragma unroll
            for (int u = 0; u < 8; u++) {
                int s = __shfl_sync(0xffffffffu, idx, j + u);
                v[u] = __ldg(&h2[(size_t)s * 32 + lane]);
            }
#pragma unroll
            for (int u = 0; u < 8; u++) {
                float2 f01 = __half22float2(*(half2*)&v[u].x);
                float2 f23 = __half22float2(*(half2*)&v[u].y);
                if (u & 1) { acc1.x += f01.x; acc1.y += f01.y; acc1.z += f23.x; acc1.w += f23.y; }
                else       { acc0.x += f01.x; acc0.y += f01.y; acc0.z += f23.x; acc0.w += f23.y; }
            }
        }
        for (; j < m; j++) {
            int s = __shfl_sync(0xffffffffu, idx, j);
            uint2 vv = __ldg(&h2[(size_t)s * 32 + lane]);
            float2 f01 = __half22float2(*(half2*)&vv.x);
            float2 f23 = __half22float2(*(half2*)&vv.y);
            acc0.x += f01.x; acc0.y += f01.y; acc0.z += f23.x; acc0.w += f23.y;
        }
    }

    float inv = 1.0f / fmaxf((float)(end - beg), 1.0f);
    float4 acc = make_float4((acc0.x + acc1.x) * inv, (acc0.y + acc1.y) * inv,
                             (acc0.z + acc1.z) * inv, (acc0.w + acc1.w) * inv);
    ((float4*)g_agg)[(size_t)n * 32 + lane] = acc;
}

// ---------------- fp16 hi/lo helpers ----------------
// v = hi + lo with hi,lo fp16; dropped term in 3-pass product is ~2^-24.
__device__ __forceinline__ uint32_t pack_hi(float a, float b, float& la, float& lb) {
    half ha = __float2half_rn(a);
    half hb = __float2half_rn(b);
    la = a - __half2float(ha);
    lb = b - __half2float(hb);
    half2 h = __halves2half2(ha, hb);     // .x (low) = a
    return *(uint32_t*)&h;
}
__device__ __forceinline__ uint32_t pack_lo(float la, float lb) {
    half2 h = __floats2half2_rn(la, lb);
    return *(uint32_t*)&h;
}

__device__ __forceinline__ void mma_f16(float c[4],
                                        uint32_t a0, uint32_t a1, uint32_t a2, uint32_t a3,
                                        uint32_t b0, uint32_t b1) {
    asm volatile(
        "mma.sync.aligned.m16n8k16.row.col.f32.f16.f16.f32 "
        "{%0,%1,%2,%3}, {%4,%5,%6,%7}, {%8,%9}, {%0,%1,%2,%3};"
        : "+f"(c[0]), "+f"(c[1]), "+f"(c[2]), "+f"(c[3])
        : "r"(a0), "r"(a1), "r"(a2), "r"(a3), "r"(b0), "r"(b1));
}

// ---------------- fused SAGE layer (tensor cores, 3xFP16 hi/lo, m16n8k16) ----------------
// out = L2normalize( [agg|f(x)] @ [Wl;Wr] + bl ), accumulates BN sum/sumsq.
// Operands packed as half2 along k: smem word [row][kpair] (A) / [kpair][n] (B).
#define A_ST 20     // [128][20] uint32 (16 kpairs + 4 pad) — conflict-free for t/t+4 pattern
#define B_ST 136    // [16][136] uint32 (128 n + 8 pad)
#define SAGE_SMEM ((2 * 128 * A_ST + 2 * 16 * B_ST + 256 + 128 + 128) * 4)

__global__ void __launch_bounds__(256, 2)
sage_mma_kernel(const float* __restrict__ x_in,
                const float* __restrict__ Wl,
                const float* __restrict__ bl,
                const float* __restrict__ Wr,
                float* __restrict__ x_out,
                int nnodes, int bn_slot, int use_bn) {
    extern __shared__ uint32_t sm[];
    uint32_t* AXhi = sm;                          // [128][A_ST]
    uint32_t* AXlo = AXhi + 128 * A_ST;
    uint32_t* Bhi  = AXlo + 128 * A_ST;           // [16][B_ST]
    uint32_t* Blo  = Bhi + 16 * B_ST;
    float* rowsumS = (float*)(Blo + 16 * B_ST);   // [128][2]
    float* colsumS = rowsumS + 256;               // [128]
    float* colsqS  = colsumS + 128;               // [128]

    const int tid = threadIdx.x;
    const int wid = tid >> 5;
    const int lane = tid & 31;
    const int g = lane >> 2;
    const int t = lane & 3;
    const int warp_m = wid & 3;      // 4 M-warps of 32 rows
    const int warp_n = wid >> 2;     // 2 N-warps of 64 cols
    const int base = blockIdx.x * 128;

    if (tid < 128) { colsumS[tid] = 0.f; colsqS[tid] = 0.f; }

    float c[2][8][4];
#pragma unroll
    for (int mt = 0; mt < 2; mt++)
#pragma unroll
        for (int nt = 0; nt < 8; nt++)
#pragma unroll
            for (int k = 0; k < 4; k++) c[mt][nt][k] = 0.f;

    for (int chunk = 0; chunk < 8; chunk++) {
        const int kBase = chunk * 32;
        const bool isX = (kBase >= 128);
        const bool bnx = isX && use_bn;
        // ---- stage AX chunk: rows 0..127, k kBase..kBase+31, half2-packed along k ----
        const float* srcA = (!isX) ? (g_agg + (size_t)base * DD + kBase)
                                   : (x_in + (size_t)base * DD + (kBase - 128));
#pragma unroll
        for (int i = 0; i < 4; i++) {
            int q = tid + i * 256;          // 0..1023 float4 granules (128 rows x 8 f4)
            int row = q >> 3;
            int f4 = q & 7;
            int grow = base + row;
            float4 v = make_float4(0.f, 0.f, 0.f, 0.f);
            if (grow < nnodes)
                v = __ldg((const float4*)(srcA + (size_t)row * DD) + f4);
            if (bnx) {
                int c4 = ((kBase - 128) >> 2) + f4;
                float4 scv = ((const float4*)g_scale)[c4];
                float4 shv = ((const float4*)g_shift)[c4];
                v.x = fmaxf(fmaf(v.x, scv.x, shv.x), 0.f);
                v.y = fmaxf(fmaf(v.y, scv.y, shv.y), 0.f);
                v.z = fmaxf(fmaf(v.z, scv.z, shv.z), 0.f);
                v.w = fmaxf(fmaf(v.w, scv.w, shv.w), 0.f);
            }
            float lx, ly, lz, lw;
            uint32_t h01 = pack_hi(v.x, v.y, lx, ly);
            uint32_t h23 = pack_hi(v.z, v.w, lz, lw);
            int kp = f4 * 2;
            AXhi[row * A_ST + kp]     = h01;
            AXhi[row * A_ST + kp + 1] = h23;
            AXlo[row * A_ST + kp]     = pack_lo(lx, ly);
            AXlo[row * A_ST + kp + 1] = pack_lo(lz, lw);
        }
        // ---- stage W chunk: rows kBase..+31 of [Wl;Wr], packed (k,k+1) per n ----
        const float* srcW = (!isX) ? (Wl + (size_t)kBase * DD)
                                   : (Wr + (size_t)(kBase - 128) * DD);
#pragma unroll
        for (int i = 0; i < 2; i++) {
            int p = tid + i * 256;          // 0..511 (16 kpairs x 32 n-float4s)
            int kk2 = p >> 5;               // kpair 0..15
            int f4 = p & 31;
            const float* r0 = srcW + (size_t)(2 * kk2) * DD + f4 * 4;
            const float* r1 = r0 + DD;
            float4 va = __ldg((const float4*)r0);
            float4 vb = __ldg((const float4*)r1);
            float l0a, l0b, l1a, l1b, l2a, l2b, l3a, l3b;
            uint32_t h0 = pack_hi(va.x, vb.x, l0a, l0b);   // half2(k, k+1) for n
            uint32_t h1 = pack_hi(va.y, vb.y, l1a, l1b);
            uint32_t h2 = pack_hi(va.z, vb.z, l2a, l2b);
            uint32_t h3 = pack_hi(va.w, vb.w, l3a, l3b);
            uint32_t* ph = Bhi + kk2 * B_ST + f4 * 4;
            uint32_t* pl = Blo + kk2 * B_ST + f4 * 4;
            ph[0] = h0; ph[1] = h1; ph[2] = h2; ph[3] = h3;
            pl[0] = pack_lo(l0a, l0b); pl[1] = pack_lo(l1a, l1b);
            pl[2] = pack_lo(l2a, l2b); pl[3] = pack_lo(l3a, l3b);
        }
        __syncthreads();

        // ---- compute 2 k-steps of 16 ----
#pragma unroll
        for (int ks = 0; ks < 2; ks++) {
            const int kp0 = ks * 8;
            uint32_t ahi[2][4], alo[2][4];
#pragma unroll
            for (int mt = 0; mt < 2; mt++) {
                int r = warp_m * 32 + mt * 16 + g;
                ahi[mt][0] = AXhi[r * A_ST + kp0 + t];
                ahi[mt][1] = AXhi[(r + 8) * A_ST + kp0 + t];
                ahi[mt][2] = AXhi[r * A_ST + kp0 + t + 4];
                ahi[mt][3] = AXhi[(r + 8) * A_ST + kp0 + t + 4];
                alo[mt][0] = AXlo[r * A_ST + kp0 + t];
                alo[mt][1] = AXlo[(r + 8) * A_ST + kp0 + t];
                alo[mt][2] = AXlo[r * A_ST + kp0 + t + 4];
                alo[mt][3] = AXlo[(r + 8) * A_ST + kp0 + t + 4];
            }
#pragma unroll
            for (int nt = 0; nt < 8; nt++) {
                int cn = warp_n * 64 + nt * 8 + g;
                uint32_t bh0 = Bhi[(kp0 + t) * B_ST + cn];
                uint32_t bh1 = Bhi[(kp0 + t + 4) * B_ST + cn];
                uint32_t bl0 = Blo[(kp0 + t) * B_ST + cn];
                uint32_t bl1 = Blo[(kp0 + t + 4) * B_ST + cn];
#pragma unroll
                for (int mt = 0; mt < 2; mt++) {
                    mma_f16(c[mt][nt], ahi[mt][0], ahi[mt][1], ahi[mt][2], ahi[mt][3], bh0, bh1);
                    mma_f16(c[mt][nt], ahi[mt][0], ahi[mt][1], ahi[mt][2], ahi[mt][3], bl0, bl1);
                    mma_f16(c[mt][nt], alo[mt][0], alo[mt][1], alo[mt][2], alo[mt][3], bh0, bh1);
                }
            }
        }
        __syncthreads();
    }

    // ---- epilogue: bias, row L2 norm, store, BN stats ----
#pragma unroll
    for (int nt = 0; nt < 8; nt++) {
        int cn = warp_n * 64 + nt * 8 + 2 * t;
        float b0v = __ldg(&bl[cn]);
        float b1v = __ldg(&bl[cn + 1]);
#pragma unroll
        for (int mt = 0; mt < 2; mt++) {
            c[mt][nt][0] += b0v; c[mt][nt][1] += b1v;
            c[mt][nt][2] += b0v; c[mt][nt][3] += b1v;
        }
    }

#pragma unroll
    for (int mt = 0; mt < 2; mt++) {
        float ssu = 0.f, ssd = 0.f;
#pragma unroll
        for (int nt = 0; nt < 8; nt++) {
            ssu += c[mt][nt][0] * c[mt][nt][0] + c[mt][nt][1] * c[mt][nt][1];
            ssd += c[mt][nt][2] * c[mt][nt][2] + c[mt][nt][3] * c[mt][nt][3];
        }
        ssu += __shfl_xor_sync(0xffffffffu, ssu, 1);
        ssu += __shfl_xor_sync(0xffffffffu, ssu, 2);
        ssd += __shfl_xor_sync(0xffffffffu, ssd, 1);
        ssd += __shfl_xor_sync(0xffffffffu, ssd, 2);
        if (t == 0) {
            int r = warp_m * 32 + mt * 16 + g;
            rowsumS[r * 2 + warp_n] = ssu;
            rowsumS[(r + 8) * 2 + warp_n] = ssd;
        }
    }
    __syncthreads();

    float p1[16], p2[16];
#pragma unroll
    for (int i = 0; i < 16; i++) { p1[i] = 0.f; p2[i] = 0.f; }

#pragma unroll
    for (int mt = 0; mt < 2; mt++) {
        int r_up = warp_m * 32 + mt * 16 + g;
        int r_dn = r_up + 8;
        float su = rowsumS[r_up * 2] + rowsumS[r_up * 2 + 1];
        float sd = rowsumS[r_dn * 2] + rowsumS[r_dn * 2 + 1];
        float invu = 1.0f / fmaxf(sqrtf(su), 1e-12f);
        float invd = 1.0f / fmaxf(sqrtf(sd), 1e-12f);
        int gu = base + r_up, gd = base + r_dn;
        bool vu = gu < nnodes, vd = gd < nnodes;
#pragma unroll
        for (int nt = 0; nt < 8; nt++) {
            int cn = warp_n * 64 + nt * 8 + 2 * t;
            if (vu) {
                float v0 = c[mt][nt][0] * invu, v1 = c[mt][nt][1] * invu;
                *(float2*)(x_out + (size_t)gu * DD + cn) = make_float2(v0, v1);
                p1[nt * 2] += v0; p2[nt * 2] += v0 * v0;
                p1[nt * 2 + 1] += v1; p2[nt * 2 + 1] += v1 * v1;
            }
            if (vd) {
                float v0 = c[mt][nt][2] * invd, v1 = c[mt][nt][3] * invd;
                *(float2*)(x_out + (size_t)gd * DD + cn) = make_float2(v0, v1);
                p1[nt * 2] += v0; p2[nt * 2] += v0 * v0;
                p1[nt * 2 + 1] += v1; p2[nt * 2 + 1] += v1 * v1;
            }
        }
    }

#pragma unroll
    for (int nt = 0; nt < 8; nt++) {
        int cn = warp_n * 64 + nt * 8 + 2 * t;
        atomicAdd(&colsumS[cn], p1[nt * 2]);
        atomicAdd(&colsqS[cn], p2[nt * 2]);
        atomicAdd(&colsumS[cn + 1], p1[nt * 2 + 1]);
        atomicAdd(&colsqS[cn + 1], p2[nt * 2 + 1]);
    }
    __syncthreads();
    if (tid < 128) {
        atomicAdd(&g_bnsum[bn_slot * DD + tid], colsumS[tid]);
        atomicAdd(&g_bnsq[bn_slot * DD + tid], colsqS[tid]);
    }
}

// ---------------- BN params from accumulated sums ----------------
__global__ void bnparams_kernel(const float* __restrict__ g,
                                const float* __restrict__ b,
                                float invN, int bn_slot) {
    int h = threadIdx.x;
    float mean = g_bnsum[bn_slot * DD + h] * invN;
    float var = g_bnsq[bn_slot * DD + h] * invN - mean * mean;
    float sc = g[h] / sqrtf(var + 1e-5f);
    g_scale[h] = sc;
    g_shift[h] = b[h] - mean * sc;
}

// ---------------- per-node dots for the prediction head (applies layer-2 BN+ReLU) ----------------
__global__ void nodedots_kernel(const float* __restrict__ Wlin) {
    int n = (blockIdx.x * blockDim.x + threadIdx.x) >> 5;
    int lane = threadIdx.x & 31;
    if (n >= NN) return;
    float4 a = ((const float4*)g_x2)[(size_t)n * 32 + lane];
    float4 sc = ((const float4*)g_scale)[lane];
    float4 sh = ((const float4*)g_shift)[lane];
    a.x = fmaxf(fmaf(a.x, sc.x, sh.x), 0.f);
    a.y = fmaxf(fmaf(a.y, sc.y, sh.y), 0.f);
    a.z = fmaxf(fmaf(a.z, sc.z, sh.z), 0.f);
    a.w = fmaxf(fmaf(a.w, sc.w, sh.w), 0.f);
    float4 w1 = __ldg(&((const float4*)Wlin)[lane]);
    float4 w2 = __ldg(&((const float4*)Wlin)[32 + lane]);
    float p = a.x * w1.x + a.y * w1.y + a.z * w1.z + a.w * w1.w;
    float q = a.x * w2.x + a.y * w2.y + a.z * w2.z + a.w * w2.w;
#pragma unroll
    for (int m = 16; m; m >>= 1) {
        p += __shfl_xor_sync(0xffffffffu, p, m);
        q += __shfl_xor_sync(0xffffffffu, q, m);
    }
    if (lane == 0) { g_p1[n] = p; g_p2[n] = q; }
}

// ---------------- final prediction: out[e] = p1[s] + p2[d] + blin ----------------
__global__ void predict_kernel(const int* __restrict__ sidx,
                               const int* __restrict__ didx,
                               const float* __restrict__ blin,
                               float* __restrict__ out, int EL) {
    int i = blockIdx.x * blockDim.x + threadIdx.x;
    if (i >= EL) return;
    int s = __ldg(&sidx[i]);
    int d = __ldg(&didx[i]);
    out[i] = g_p1[s] + g_p2[d] + blin[0];
}

// ---------------- launcher ----------------
extern "C" void kernel_launch(void* const* d_in, const int* in_sizes, int n_in,
                              void* d_out, int out_size) {
    const int*   edge_index = (const int*)d_in[0];     // [2, E]
    const int*   elabel     = (const int*)d_in[1];     // [2, EL]
    const float* emb        = (const float*)d_in[2];   // [N, 128]
    const float* Wl1  = (const float*)d_in[3];
    const float* bl1  = (const float*)d_in[4];
    const float* Wr1  = (const float*)d_in[5];
    const float* g1   = (const float*)d_in[6];
    const float* b1   = (const float*)d_in[7];
    const float* Wl2  = (const float*)d_in[8];
    const float* bl2  = (const float*)d_in[9];
    const float* Wr2  = (const float*)d_in[10];
    const float* g2   = (const float*)d_in[11];
    const float* b2   = (const float*)d_in[12];
    const float* Wlin = (const float*)d_in[13];
    const float* blin = (const float*)d_in[14];

    const int E  = in_sizes[0] / 2;
    const int EL = in_sizes[1] / 2;
    const int n  = in_sizes[2] / DD;
    float* out = (float*)d_out;

    cudaFuncSetAttribute(sage_mma_kernel, cudaFuncAttributeMaxDynamicSharedMemorySize, SAGE_SMEM);

    void *p_x1 = nullptr, *p_x2 = nullptr;
    cudaGetSymbolAddress(&p_x1, g_x1);
    cudaGetSymbolAddress(&p_x2, g_x2);
    float* x1 = (float*)p_x1;
    float* x2 = (float*)p_x2;

    const int eblocks = (E + 255) / 256;
    const int gblocks = (n + 127) / 128;
    const int cblocks = (n * (DD / 4) + 255) / 256;  // convert kernels
    const int wblocks = (n + 7) / 8;
    const float invN = 1.0f / (float)n;

    // ---- CSR build (once; reused by both layers) ----
    init_kernel<<<(NN + 255) / 256, 256>>>();
    hist_kernel<<<eblocks, 256>>>(edge_index + E, E);
    scan1_kernel<<<SCAN_BLOCKS, 1024>>>();
    scan2_kernel<<<1, 128>>>();
    scan3_kernel<<<SCAN_BLOCKS, 1024>>>();
    fill_kernel<<<eblocks, 256>>>(edge_index, edge_index + E, E);

    // ---- layer 1: fp16 copy of emb -> aggregate -> GEMM ----
    tohalf_kernel<false><<<cblocks, 256>>>(emb, n * (DD / 4));
    aggregate_kernel<<<wblocks, 256>>>();
    sage_mma_kernel<<<gblocks, 256, SAGE_SMEM>>>(emb, Wl1, bl1, Wr1, x1, n, 0, 0);
    bnparams_kernel<<<1, 128>>>(g1, b1, invN, 0);   // -> scale/shift = layer-1 BN

    // ---- layer 2: fp16 copy of relu(bn(x1)) -> aggregate -> GEMM (X-side BN fused fp32) ----
    tohalf_kernel<true><<<cblocks, 256>>>(x1, n * (DD / 4));
    aggregate_kernel<<<wblocks, 256>>>();
    sage_mma_kernel<<<gblocks, 256, SAGE_SMEM>>>(x1, Wl2, bl2, Wr2, x2, n, 1, 1);
    bnparams_kernel<<<1, 128>>>(g2, b2, invN, 1);   // -> scale/shift = layer-2 BN

    // ---- head (BN+ReLU of x2 fused into nodedots) ----
    nodedots_kernel<<<wblocks, 256>>>(Wlin);
    predict_kernel<<<(EL + 255) / 256, 256>>>(elabel, elabel + EL, blin, out, EL);
}

// round 11
// speedup vs baseline: 1.0275x; 1.0275x over previous
#include <cuda_runtime.h>
#include <cuda_fp16.h>
#include <math.h>
#include <stdint.h>

// Problem constants (fixed by the dataset)
#define NN 100000   // nodes
#define DD 128      // feature dim (= hidden dim)
#define EE 1600000  // edges
#define SCAN_BLOCKS 98   // ceil(NN/1024)

// ---------------- scratch (static device globals; no allocation) ----------------
__device__ __align__(16) float g_agg[NN * DD];
__device__ __align__(16) float g_x1[NN * DD];
__device__ __align__(16) float g_x2[NN * DD];
__device__ __align__(16) __half g_h[NN * DD];   // fp16 copy of gather source
__device__ int   g_deg[NN];
__device__ int   g_off[NN + 1];
__device__ int   g_cursor[NN];
__device__ int   g_csr[EE];
__device__ int   g_part[128];
__device__ float g_bnsum[2 * DD];
__device__ float g_bnsq[2 * DD];
__device__ __align__(16) float g_scale[DD];
__device__ __align__(16) float g_shift[DD];
__device__ float g_p1[NN];
__device__ float g_p2[NN];

// ---------------- init: zero deg + BN accumulators ----------------
__global__ void init_kernel() {
    int i = blockIdx.x * blockDim.x + threadIdx.x;
    if (i < NN) g_deg[i] = 0;
    if (i < 2 * DD) { g_bnsum[i] = 0.f; g_bnsq[i] = 0.f; }
}

// ---------------- degree histogram ----------------
__global__ void hist_kernel(const int* __restrict__ dst, int E) {
    int i = blockIdx.x * blockDim.x + threadIdx.x;
    if (i < E) atomicAdd(&g_deg[__ldg(&dst[i])], 1);
}

// ---------------- parallel scan, phase 1: per-chunk sums ----------------
__global__ void scan1_kernel() {
    __shared__ int warp_sums[32];
    int t = threadIdx.x;
    int i = blockIdx.x * 1024 + t;
    int v = (i < NN) ? g_deg[i] : 0;
#pragma unroll
    for (int m = 16; m; m >>= 1) v += __shfl_xor_sync(0xffffffffu, v, m);
    if ((t & 31) == 0) warp_sums[t >> 5] = v;
    __syncthreads();
    if (t < 32) {
        int s = warp_sums[t];
#pragma unroll
        for (int m = 16; m; m >>= 1) s += __shfl_xor_sync(0xffffffffu, s, m);
        if (t == 0) g_part[blockIdx.x] = s;
    }
}

// ---------------- parallel scan, phase 2: scan the 98 partials ----------------
__global__ void scan2_kernel() {
    __shared__ int sm2[128];
    int t = threadIdx.x;
    int v = (t < SCAN_BLOCKS) ? g_part[t] : 0;
    sm2[t] = v;
    __syncthreads();
    for (int d = 1; d < 128; d <<= 1) {
        int y = (t >= d) ? sm2[t - d] : 0;
        __syncthreads();
        sm2[t] += y;
        __syncthreads();
    }
    if (t < SCAN_BLOCKS) g_part[t] = sm2[t] - v;       // exclusive prefix
    if (t == SCAN_BLOCKS - 1) g_off[NN] = sm2[t];      // total = E
}

// ---------------- parallel scan, phase 3: block exclusive scan + base ----------------
__global__ void scan3_kernel() {
    __shared__ int warp_sums[32];
    int t = threadIdx.x;
    int lane = t & 31, wid = t >> 5;
    int i = blockIdx.x * 1024 + t;
    int v = (i < NN) ? g_deg[i] : 0;
    int x = v;
#pragma unroll
    for (int d = 1; d < 32; d <<= 1) {
        int y = __shfl_up_sync(0xffffffffu, x, d);
        if (lane >= d) x += y;
    }
    if (lane == 31) warp_sums[wid] = x;
    __syncthreads();
    if (wid == 0) {
        int s = warp_sums[lane];
#pragma unroll
        for (int d = 1; d < 32; d <<= 1) {
            int y = __shfl_up_sync(0xffffffffu, s, d);
            if (lane >= d) s += y;
        }
        warp_sums[lane] = s;   // inclusive warp-total scan
    }
    __syncthreads();
    int base = g_part[blockIdx.x] + (wid ? warp_sums[wid - 1] : 0);
    int excl = base + x - v;
    if (i < NN) { g_off[i] = excl; g_cursor[i] = excl; }
}

// ---------------- fill CSR: csr[slot] = src, keyed by dst ----------------
__global__ void fill_kernel(const int* __restrict__ src,
                            const int* __restrict__ dst, int E) {
    int i = blockIdx.x * blockDim.x + threadIdx.x;
    if (i >= E) return;
    int d = __ldg(&dst[i]);
    int slot = atomicAdd(&g_cursor[d], 1);
    g_csr[slot] = __ldg(&src[i]);
}

// ---------------- convert to fp16 (optionally fused BN+ReLU) ----------------
template <bool BN>
__global__ void tohalf_kernel(const float* __restrict__ x, int total4) {
    int i = blockIdx.x * blockDim.x + threadIdx.x;
    if (i >= total4) return;
    float4 v = __ldg(&((const float4*)x)[i]);
    if (BN) {
        int c4 = i & 31;
        float4 sc = ((const float4*)g_scale)[c4];
        float4 sh = ((const float4*)g_shift)[c4];
        v.x = fmaxf(fmaf(v.x, sc.x, sh.x), 0.f);
        v.y = fmaxf(fmaf(v.y, sc.y, sh.y), 0.f);
        v.z = fmaxf(fmaf(v.z, sc.z, sh.z), 0.f);
        v.w = fmaxf(fmaf(v.w, sc.w, sh.w), 0.f);
    }
    uint2 o;
    half2 h01 = __floats2half2_rn(v.x, v.y);
    half2 h23 = __floats2half2_rn(v.z, v.w);
    o.x = *(uint32_t*)&h01;
    o.y = *(uint32_t*)&h23;
    ((uint2*)g_h)[i] = o;
}

// ---------------- pull aggregation from fp16 rows (16B lane loads, 2 nodes/warp) ----------------
// Each half-warp (16 lanes x uint4 = 256 B) owns one node; halves the LDG count
// vs uint2 lanes. Indices fetched 16-at-a-time coalesced, broadcast by width-16
// shuffle with per-half masks (halves stay converged within themselves).
__global__ void aggregate_kernel() {
    int gw = (blockIdx.x * blockDim.x + threadIdx.x) >> 5;
    int lane = threadIdx.x & 31;
    int half_id = lane >> 4;            // 0 or 1
    int sub = lane & 15;                // lane within half-warp
    int n = gw * 2 + half_id;
    if (n >= NN) return;
    unsigned mask = half_id ? 0xFFFF0000u : 0x0000FFFFu;
    int beg = __ldg(&g_off[n]);
    int end = __ldg(&g_off[n + 1]);
    const uint4* h4 = (const uint4*)g_h;   // row = 16 uint4 (256 B)

    float acc[8];
#pragma unroll
    for (int i = 0; i < 8; i++) acc[i] = 0.f;

    for (int cbase = beg; cbase < end; cbase += 16) {
        int m = min(16, end - cbase);
        int idx = (sub < m) ? __ldg(&g_csr[cbase + sub]) : 0;
        int j = 0;
        for (; j + 4 <= m; j += 4) {
            uint4 v[4];
#pragma unroll
            for (int u = 0; u < 4; u++) {
                int s = __shfl_sync(mask, idx, j + u, 16);
                v[u] = __ldg(&h4[(size_t)s * 16 + sub]);
            }
#pragma unroll
            for (int u = 0; u < 4; u++) {
                float2 f0 = __half22float2(*(half2*)&v[u].x);
                float2 f1 = __half22float2(*(half2*)&v[u].y);
                float2 f2 = __half22float2(*(half2*)&v[u].z);
                float2 f3 = __half22float2(*(half2*)&v[u].w);
                acc[0] += f0.x; acc[1] += f0.y;
                acc[2] += f1.x; acc[3] += f1.y;
                acc[4] += f2.x; acc[5] += f2.y;
                acc[6] += f3.x; acc[7] += f3.y;
            }
        }
        for (; j < m; j++) {
            int s = __shfl_sync(mask, idx, j, 16);
            uint4 vv = __ldg(&h4[(size_t)s * 16 + sub]);
            float2 f0 = __half22float2(*(half2*)&vv.x);
            float2 f1 = __half22float2(*(half2*)&vv.y);
            float2 f2 = __half22float2(*(half2*)&vv.z);
            float2 f3 = __half22float2(*(half2*)&vv.w);
            acc[0] += f0.x; acc[1] += f0.y;
            acc[2] += f1.x; acc[3] += f1.y;
            acc[4] += f2.x; acc[5] += f2.y;
            acc[6] += f3.x; acc[7] += f3.y;
        }
    }

    float inv = 1.0f / fmaxf((float)(end - beg), 1.0f);
    float4* outp = (float4*)g_agg + (size_t)n * 32 + sub * 2;
    outp[0] = make_float4(acc[0] * inv, acc[1] * inv, acc[2] * inv, acc[3] * inv);
    outp[1] = make_float4(acc[4] * inv, acc[5] * inv, acc[6] * inv, acc[7] * inv);
}

// ---------------- fp16 hi/lo helpers ----------------
__device__ __forceinline__ uint32_t pack_hi(float a, float b, float& la, float& lb) {
    half ha = __float2half_rn(a);
    half hb = __float2half_rn(b);
    la = a - __half2float(ha);
    lb = b - __half2float(hb);
    half2 h = __halves2half2(ha, hb);     // .x (low) = a
    return *(uint32_t*)&h;
}
__device__ __forceinline__ uint32_t pack_lo(float la, float lb) {
    half2 h = __floats2half2_rn(la, lb);
    return *(uint32_t*)&h;
}

__device__ __forceinline__ void mma_f16(float c[4],
                                        uint32_t a0, uint32_t a1, uint32_t a2, uint32_t a3,
                                        uint32_t b0, uint32_t b1) {
    asm volatile(
        "mma.sync.aligned.m16n8k16.row.col.f32.f16.f16.f32 "
        "{%0,%1,%2,%3}, {%4,%5,%6,%7}, {%8,%9}, {%0,%1,%2,%3};"
        : "+f"(c[0]), "+f"(c[1]), "+f"(c[2]), "+f"(c[3])
        : "r"(a0), "r"(a1), "r"(a2), "r"(a3), "r"(b0), "r"(b1));
}

// ---------------- fused SAGE layer (tensor cores, 3xFP16 hi/lo, m16n8k16) ----------------
#define A_ST 20     // [128][20] uint32 (16 kpairs + 4 pad)
#define B_ST 136    // [16][136] uint32 (128 n + 8 pad)
#define SAGE_SMEM ((2 * 128 * A_ST + 2 * 16 * B_ST + 256 + 128 + 128) * 4)

__global__ void __launch_bounds__(256, 2)
sage_mma_kernel(const float* __restrict__ x_in,
                const float* __restrict__ Wl,
                const float* __restrict__ bl,
                const float* __restrict__ Wr,
                float* __restrict__ x_out,
                int nnodes, int bn_slot, int use_bn) {
    extern __shared__ uint32_t sm[];
    uint32_t* AXhi = sm;                          // [128][A_ST]
    uint32_t* AXlo = AXhi + 128 * A_ST;
    uint32_t* Bhi  = AXlo + 128 * A_ST;           // [16][B_ST]
    uint32_t* Blo  = Bhi + 16 * B_ST;
    float* rowsumS = (float*)(Blo + 16 * B_ST);   // [128][2]
    float* colsumS = rowsumS + 256;               // [128]
    float* colsqS  = colsumS + 128;               // [128]

    const int tid = threadIdx.x;
    const int wid = tid >> 5;
    const int lane = tid & 31;
    const int g = lane >> 2;
    const int t = lane & 3;
    const int warp_m = wid & 3;      // 4 M-warps of 32 rows
    const int warp_n = wid >> 2;     // 2 N-warps of 64 cols
    const int base = blockIdx.x * 128;

    if (tid < 128) { colsumS[tid] = 0.f; colsqS[tid] = 0.f; }

    float c[2][8][4];
#pragma unroll
    for (int mt = 0; mt < 2; mt++)
#pragma unroll
        for (int nt = 0; nt < 8; nt++)
#pragma unroll
            for (int k = 0; k < 4; k++) c[mt][nt][k] = 0.f;

    for (int chunk = 0; chunk < 8; chunk++) {
        const int kBase = chunk * 32;
        const bool isX = (kBase >= 128);
        const bool bnx = isX && use_bn;
        // ---- stage AX chunk: rows 0..127, k kBase..kBase+31, half2-packed along k ----
        const float* srcA = (!isX) ? (g_agg + (size_t)base * DD + kBase)
                                   : (x_in + (size_t)base * DD + (kBase - 128));
#pragma unroll
        for (int i = 0; i < 4; i++) {
            int q = tid + i * 256;          // 0..1023 float4 granules (128 rows x 8 f4)
            int row = q >> 3;
            int f4 = q & 7;
            int grow = base + row;
            float4 v = make_float4(0.f, 0.f, 0.f, 0.f);
            if (grow < nnodes)
                v = __ldg((const float4*)(srcA + (size_t)row * DD) + f4);
            if (bnx) {
                int c4 = ((kBase - 128) >> 2) + f4;
                float4 scv = ((const float4*)g_scale)[c4];
                float4 shv = ((const float4*)g_shift)[c4];
                v.x = fmaxf(fmaf(v.x, scv.x, shv.x), 0.f);
                v.y = fmaxf(fmaf(v.y, scv.y, shv.y), 0.f);
                v.z = fmaxf(fmaf(v.z, scv.z, shv.z), 0.f);
                v.w = fmaxf(fmaf(v.w, scv.w, shv.w), 0.f);
            }
            float lx, ly, lz, lw;
            uint32_t h01 = pack_hi(v.x, v.y, lx, ly);
            uint32_t h23 = pack_hi(v.z, v.w, lz, lw);
            int kp = f4 * 2;
            AXhi[row * A_ST + kp]     = h01;
            AXhi[row * A_ST + kp + 1] = h23;
            AXlo[row * A_ST + kp]     = pack_lo(lx, ly);
            AXlo[row * A_ST + kp + 1] = pack_lo(lz, lw);
        }
        // ---- stage W chunk: rows kBase..+31 of [Wl;Wr], packed (k,k+1) per n ----
        const float* srcW = (!isX) ? (Wl + (size_t)kBase * DD)
                                   : (Wr + (size_t)(kBase - 128) * DD);
#pragma unroll
        for (int i = 0; i < 2; i++) {
            int p = tid + i * 256;          // 0..511 (16 kpairs x 32 n-float4s)
            int kk2 = p >> 5;               // kpair 0..15
            int f4 = p & 31;
            const float* r0 = srcW + (size_t)(2 * kk2) * DD + f4 * 4;
            const float* r1 = r0 + DD;
            float4 va = __ldg((const float4*)r0);
            float4 vb = __ldg((const float4*)r1);
            float l0a, l0b, l1a, l1b, l2a, l2b, l3a, l3b;
            uint32_t h0 = pack_hi(va.x, vb.x, l0a, l0b);   // half2(k, k+1) for n
            uint32_t h1 = pack_hi(va.y, vb.y, l1a, l1b);
            uint32_t h2 = pack_hi(va.z, vb.z, l2a, l2b);
            uint32_t h3 = pack_hi(va.w, vb.w, l3a, l3b);
            uint32_t* ph = Bhi + kk2 * B_ST + f4 * 4;
            uint32_t* pl = Blo + kk2 * B_ST + f4 * 4;
            ph[0] = h0; ph[1] = h1; ph[2] = h2; ph[3] = h3;
            pl[0] = pack_lo(l0a, l0b); pl[1] = pack_lo(l1a, l1b);
            pl[2] = pack_lo(l2a, l2b); pl[3] = pack_lo(l3a, l3b);
        }
        __syncthreads();

        // ---- compute 2 k-steps of 16 ----
#pragma unroll
        for (int ks = 0; ks < 2; ks++) {
            const int kp0 = ks * 8;
            uint32_t ahi[2][4], alo[2][4];
#pragma unroll
            for (int mt = 0; mt < 2; mt++) {
                int r = warp_m * 32 + mt * 16 + g;
                ahi[mt][0] = AXhi[r * A_ST + kp0 + t];
                ahi[mt][1] = AXhi[(r + 8) * A_ST + kp0 + t];
                ahi[mt][2] = AXhi[r * A_ST + kp0 + t + 4];
                ahi[mt][3] = AXhi[(r + 8) * A_ST + kp0 + t + 4];
                alo[mt][0] = AXlo[r * A_ST + kp0 + t];
                alo[mt][1] = AXlo[(r + 8) * A_ST + kp0 + t];
                alo[mt][2] = AXlo[r * A_ST + kp0 + t + 4];
                alo[mt][3] = AXlo[(r + 8) * A_ST + kp0 + t + 4];
            }
#pragma unroll
            for (int nt = 0; nt < 8; nt++) {
                int cn = warp_n * 64 + nt * 8 + g;
                uint32_t bh0 = Bhi[(kp0 + t) * B_ST + cn];
                uint32_t bh1 = Bhi[(kp0 + t + 4) * B_ST + cn];
                uint32_t bl0 = Blo[(kp0 + t) * B_ST + cn];
                uint32_t bl1 = Blo[(kp0 + t + 4) * B_ST + cn];
#pragma unroll
                for (int mt = 0; mt < 2; mt++) {
                    mma_f16(c[mt][nt], ahi[mt][0], ahi[mt][1], ahi[mt][2], ahi[mt][3], bh0, bh1);
                    mma_f16(c[mt][nt], ahi[mt][0], ahi[mt][1], ahi[mt][2], ahi[mt][3], bl0, bl1);
                    mma_f16(c[mt][nt], alo[mt][0], alo[mt][1], alo[mt][2], alo[mt][3], bh0, bh1);
                }
            }
        }
        __syncthreads();
    }

    // ---- epilogue: bias, row L2 norm, store, BN stats ----
#pragma unroll
    for (int nt = 0; nt < 8; nt++) {
        int cn = warp_n * 64 + nt * 8 + 2 * t;
        float b0v = __ldg(&bl[cn]);
        float b1v = __ldg(&bl[cn + 1]);
#pragma unroll
        for (int mt = 0; mt < 2; mt++) {
            c[mt][nt][0] += b0v; c[mt][nt][1] += b1v;
            c[mt][nt][2] += b0v; c[mt][nt][3] += b1v;
        }
    }

#pragma unroll
    for (int mt = 0; mt < 2; mt++) {
        float ssu = 0.f, ssd = 0.f;
#pragma unroll
        for (int nt = 0; nt < 8; nt++) {
            ssu += c[mt][nt][0] * c[mt][nt][0] + c[mt][nt][1] * c[mt][nt][1];
            ssd += c[mt][nt][2] * c[mt][nt][2] + c[mt][nt][3] * c[mt][nt][3];
        }
        ssu += __shfl_xor_sync(0xffffffffu, ssu, 1);
        ssu += __shfl_xor_sync(0xffffffffu, ssu, 2);
        ssd += __shfl_xor_sync(0xffffffffu, ssd, 1);
        ssd += __shfl_xor_sync(0xffffffffu, ssd, 2);
        if (t == 0) {
            int r = warp_m * 32 + mt * 16 + g;
            rowsumS[r * 2 + warp_n] = ssu;
            rowsumS[(r + 8) * 2 + warp_n] = ssd;
        }
    }
    __syncthreads();

    float p1[16], p2[16];
#pragma unroll
    for (int i = 0; i < 16; i++) { p1[i] = 0.f; p2[i] = 0.f; }

#pragma unroll
    for (int mt = 0; mt < 2; mt++) {
        int r_up = warp_m * 32 + mt * 16 + g;
        int r_dn = r_up + 8;
        float su = rowsumS[r_up * 2] + rowsumS[r_up * 2 + 1];
        float sd = rowsumS[r_dn * 2] + rowsumS[r_dn * 2 + 1];
        float invu = 1.0f / fmaxf(sqrtf(su), 1e-12f);
        float invd = 1.0f / fmaxf(sqrtf(sd), 1e-12f);
        int gu = base + r_up, gd = base + r_dn;
        bool vu = gu < nnodes, vd = gd < nnodes;
#pragma unroll
        for (int nt = 0; nt < 8; nt++) {
            int cn = warp_n * 64 + nt * 8 + 2 * t;
            if (vu) {
                float v0 = c[mt][nt][0] * invu, v1 = c[mt][nt][1] * invu;
                *(float2*)(x_out + (size_t)gu * DD + cn) = make_float2(v0, v1);
                p1[nt * 2] += v0; p2[nt * 2] += v0 * v0;
                p1[nt * 2 + 1] += v1; p2[nt * 2 + 1] += v1 * v1;
            }
            if (vd) {
                float v0 = c[mt][nt][2] * invd, v1 = c[mt][nt][3] * invd;
                *(float2*)(x_out + (size_t)gd * DD + cn) = make_float2(v0, v1);
                p1[nt * 2] += v0; p2[nt * 2] += v0 * v0;
                p1[nt * 2 + 1] += v1; p2[nt * 2 + 1] += v1 * v1;
            }
        }
    }

#pragma unroll
    for (int nt = 0; nt < 8; nt++) {
        int cn = warp_n * 64 + nt * 8 + 2 * t;
        atomicAdd(&colsumS[cn], p1[nt * 2]);
        atomicAdd(&colsqS[cn], p2[nt * 2]);
        atomicAdd(&colsumS[cn + 1], p1[nt * 2 + 1]);
        atomicAdd(&colsqS[cn + 1], p2[nt * 2 + 1]);
    }
    __syncthreads();
    if (tid < 128) {
        atomicAdd(&g_bnsum[bn_slot * DD + tid], colsumS[tid]);
        atomicAdd(&g_bnsq[bn_slot * DD + tid], colsqS[tid]);
    }
}

// ---------------- BN params from accumulated sums ----------------
__global__ void bnparams_kernel(const float* __restrict__ g,
                                const float* __restrict__ b,
                                float invN, int bn_slot) {
    int h = threadIdx.x;
    float mean = g_bnsum[bn_slot * DD + h] * invN;
    float var = g_bnsq[bn_slot * DD + h] * invN - mean * mean;
    float sc = g[h] / sqrtf(var + 1e-5f);
    g_scale[h] = sc;
    g_shift[h] = b[h] - mean * sc;
}

// ---------------- per-node dots for the prediction head (applies layer-2 BN+ReLU) ----------------
__global__ void nodedots_kernel(const float* __restrict__ Wlin) {
    int n = (blockIdx.x * blockDim.x + threadIdx.x) >> 5;
    int lane = threadIdx.x & 31;
    if (n >= NN) return;
    float4 a = ((const float4*)g_x2)[(size_t)n * 32 + lane];
    float4 sc = ((const float4*)g_scale)[lane];
    float4 sh = ((const float4*)g_shift)[lane];
    a.x = fmaxf(fmaf(a.x, sc.x, sh.x), 0.f);
    a.y = fmaxf(fmaf(a.y, sc.y, sh.y), 0.f);
    a.z = fmaxf(fmaf(a.z, sc.z, sh.z), 0.f);
    a.w = fmaxf(fmaf(a.w, sc.w, sh.w), 0.f);
    float4 w1 = __ldg(&((const float4*)Wlin)[lane]);
    float4 w2 = __ldg(&((const float4*)Wlin)[32 + lane]);
    float p = a.x * w1.x + a.y * w1.y + a.z * w1.z + a.w * w1.w;
    float q = a.x * w2.x + a.y * w2.y + a.z * w2.z + a.w * w2.w;
#pragma unroll
    for (int m = 16; m; m >>= 1) {
        p += __shfl_xor_sync(0xffffffffu, p, m);
        q += __shfl_xor_sync(0xffffffffu, q, m);
    }
    if (lane == 0) { g_p1[n] = p; g_p2[n] = q; }
}

// ---------------- final prediction: out[e] = p1[s] + p2[d] + blin ----------------
__global__ void predict_kernel(const int* __restrict__ sidx,
                               const int* __restrict__ didx,
                               const float* __restrict__ blin,
                               float* __restrict__ out, int EL) {
    int i = blockIdx.x * blockDim.x + threadIdx.x;
    if (i >= EL) return;
    int s = __ldg(&sidx[i]);
    int d = __ldg(&didx[i]);
    out[i] = g_p1[s] + g_p2[d] + blin[0];
}

// ---------------- launcher ----------------
extern "C" void kernel_launch(void* const* d_in, const int* in_sizes, int n_in,
                              void* d_out, int out_size) {
    const int*   edge_index = (const int*)d_in[0];     // [2, E]
    const int*   elabel     = (const int*)d_in[1];     // [2, EL]
    const float* emb        = (const float*)d_in[2];   // [N, 128]
    const float* Wl1  = (const float*)d_in[3];
    const float* bl1  = (const float*)d_in[4];
    const float* Wr1  = (const float*)d_in[5];
    const float* g1   = (const float*)d_in[6];
    const float* b1   = (const float*)d_in[7];
    const float* Wl2  = (const float*)d_in[8];
    const float* bl2  = (const float*)d_in[9];
    const float* Wr2  = (const float*)d_in[10];
    const float* g2   = (const float*)d_in[11];
    const float* b2   = (const float*)d_in[12];
    const float* Wlin = (const float*)d_in[13];
    const float* blin = (const float*)d_in[14];

    const int E  = in_sizes[0] / 2;
    const int EL = in_sizes[1] / 2;
    const int n  = in_sizes[2] / DD;
    float* out = (float*)d_out;

    cudaFuncSetAttribute(sage_mma_kernel, cudaFuncAttributeMaxDynamicSharedMemorySize, SAGE_SMEM);

    void *p_x1 = nullptr, *p_x2 = nullptr;
    cudaGetSymbolAddress(&p_x1, g_x1);
    cudaGetSymbolAddress(&p_x2, g_x2);
    float* x1 = (float*)p_x1;
    float* x2 = (float*)p_x2;

    const int eblocks = (E + 255) / 256;
    const int gblocks = (n + 127) / 128;
    const int cblocks = (n * (DD / 4) + 255) / 256;  // convert kernels
    const int wblocks = (n + 7) / 8;                 // warp-per-node kernels
    const int a2blocks = (n + 15) / 16;              // 2-nodes-per-warp aggregate
    const float invN = 1.0f / (float)n;

    // ---- CSR build (once; reused by both layers) ----
    init_kernel<<<(NN + 255) / 256, 256>>>();
    hist_kernel<<<eblocks, 256>>>(edge_index + E, E);
    scan1_kernel<<<SCAN_BLOCKS, 1024>>>();
    scan2_kernel<<<1, 128>>>();
    scan3_kernel<<<SCAN_BLOCKS, 1024>>>();
    fill_kernel<<<eblocks, 256>>>(edge_index, edge_index + E, E);

    // ---- layer 1: fp16 copy of emb -> aggregate -> GEMM ----
    tohalf_kernel<false><<<cblocks, 256>>>(emb, n * (DD / 4));
    aggregate_kernel<<<a2blocks, 256>>>();
    sage_mma_kernel<<<gblocks, 256, SAGE_SMEM>>>(emb, Wl1, bl1, Wr1, x1, n, 0, 0);
    bnparams_kernel<<<1, 128>>>(g1, b1, invN, 0);   // -> scale/shift = layer-1 BN

    // ---- layer 2: fp16 copy of relu(bn(x1)) -> aggregate -> GEMM (X-side BN fused fp32) ----
    tohalf_kernel<true><<<cblocks, 256>>>(x1, n * (DD / 4));
    aggregate_kernel<<<a2blocks, 256>>>();
    sage_mma_kernel<<<gblocks, 256, SAGE_SMEM>>>(x1, Wl2, bl2, Wr2, x2, n, 1, 1);
    bnparams_kernel<<<1, 128>>>(g2, b2, invN, 1);   // -> scale/shift = layer-2 BN

    // ---- head (BN+ReLU of x2 fused into nodedots) ----
    nodedots_kernel<<<wblocks, 256>>>(Wlin);
    predict_kernel<<<(EL + 255) / 256, 256>>>(elabel, elabel + EL, blin, out, EL);
}

// round 12
// speedup vs baseline: 1.0296x; 1.0020x over previous
#include <cuda_runtime.h>
#include <cuda_fp16.h>
#include <math.h>
#include <stdint.h>

// Problem constants (fixed by the dataset)
#define NN 100000   // nodes
#define DD 128      // feature dim (= hidden dim)
#define EE 1600000  // edges
#define SCAN_BLOCKS 98   // ceil(NN/1024)

// ---------------- scratch (static device globals; no allocation) ----------------
__device__ __align__(16) float g_agg[NN * DD];
__device__ __align__(16) float g_x1[NN * DD];
__device__ __align__(16) float g_x2[NN * DD];
__device__ __align__(16) __half g_h[NN * DD];   // fp16 copy of gather source
__device__ int   g_deg[NN];
__device__ int   g_off[NN + 1];
__device__ int   g_cursor[NN];
__device__ int   g_csr[EE];
__device__ int   g_part[128];
__device__ float g_bnsum[2 * DD];
__device__ float g_bnsq[2 * DD];
__device__ __align__(16) float g_scale[DD];
__device__ __align__(16) float g_shift[DD];
__device__ float g_p1[NN];
__device__ float g_p2[NN];

// ---------------- init: zero deg + BN accumulators ----------------
__global__ void init_kernel() {
    int i = blockIdx.x * blockDim.x + threadIdx.x;
    if (i < NN) g_deg[i] = 0;
    if (i < 2 * DD) { g_bnsum[i] = 0.f; g_bnsq[i] = 0.f; }
}

// ---------------- degree histogram ----------------
__global__ void hist_kernel(const int* __restrict__ dst, int E) {
    int i = blockIdx.x * blockDim.x + threadIdx.x;
    if (i < E) atomicAdd(&g_deg[__ldg(&dst[i])], 1);
}

// ---------------- parallel scan, phase 1: per-chunk sums ----------------
__global__ void scan1_kernel() {
    __shared__ int warp_sums[32];
    int t = threadIdx.x;
    int i = blockIdx.x * 1024 + t;
    int v = (i < NN) ? g_deg[i] : 0;
#pragma unroll
    for (int m = 16; m; m >>= 1) v += __shfl_xor_sync(0xffffffffu, v, m);
    if ((t & 31) == 0) warp_sums[t >> 5] = v;
    __syncthreads();
    if (t < 32) {
        int s = warp_sums[t];
#pragma unroll
        for (int m = 16; m; m >>= 1) s += __shfl_xor_sync(0xffffffffu, s, m);
        if (t == 0) g_part[blockIdx.x] = s;
    }
}

// ---------------- parallel scan, phase 2: scan the 98 partials ----------------
__global__ void scan2_kernel() {
    __shared__ int sm2[128];
    int t = threadIdx.x;
    int v = (t < SCAN_BLOCKS) ? g_part[t] : 0;
    sm2[t] = v;
    __syncthreads();
    for (int d = 1; d < 128; d <<= 1) {
        int y = (t >= d) ? sm2[t - d] : 0;
        __syncthreads();
        sm2[t] += y;
        __syncthreads();
    }
    if (t < SCAN_BLOCKS) g_part[t] = sm2[t] - v;       // exclusive prefix
    if (t == SCAN_BLOCKS - 1) g_off[NN] = sm2[t];      // total = E
}

// ---------------- parallel scan, phase 3: block exclusive scan + base ----------------
__global__ void scan3_kernel() {
    __shared__ int warp_sums[32];
    int t = threadIdx.x;
    int lane = t & 31, wid = t >> 5;
    int i = blockIdx.x * 1024 + t;
    int v = (i < NN) ? g_deg[i] : 0;
    int x = v;
#pragma unroll
    for (int d = 1; d < 32; d <<= 1) {
        int y = __shfl_up_sync(0xffffffffu, x, d);
        if (lane >= d) x += y;
    }
    if (lane == 31) warp_sums[wid] = x;
    __syncthreads();
    if (wid == 0) {
        int s = warp_sums[lane];
#pragma unroll
        for (int d = 1; d < 32; d <<= 1) {
            int y = __shfl_up_sync(0xffffffffu, s, d);
            if (lane >= d) s += y;
        }
        warp_sums[lane] = s;   // inclusive warp-total scan
    }
    __syncthreads();
    int base = g_part[blockIdx.x] + (wid ? warp_sums[wid - 1] : 0);
    int excl = base + x - v;
    if (i < NN) { g_off[i] = excl; g_cursor[i] = excl; }
}

// ---------------- fill CSR: csr[slot] = src, keyed by dst ----------------
__global__ void fill_kernel(const int* __restrict__ src,
                            const int* __restrict__ dst, int E) {
    int i = blockIdx.x * blockDim.x + threadIdx.x;
    if (i >= E) return;
    int d = __ldg(&dst[i]);
    int slot = atomicAdd(&g_cursor[d], 1);
    g_csr[slot] = __ldg(&src[i]);
}

// ---------------- convert to fp16 (optionally fused BN+ReLU) ----------------
template <bool BN>
__global__ void tohalf_kernel(const float* __restrict__ x, int total4) {
    int i = blockIdx.x * blockDim.x + threadIdx.x;
    if (i >= total4) return;
    float4 v = __ldg(&((const float4*)x)[i]);
    if (BN) {
        int c4 = i & 31;
        float4 sc = ((const float4*)g_scale)[c4];
        float4 sh = ((const float4*)g_shift)[c4];
        v.x = fmaxf(fmaf(v.x, sc.x, sh.x), 0.f);
        v.y = fmaxf(fmaf(v.y, sc.y, sh.y), 0.f);
        v.z = fmaxf(fmaf(v.z, sc.z, sh.z), 0.f);
        v.w = fmaxf(fmaf(v.w, sc.w, sh.w), 0.f);
    }
    uint2 o;
    half2 h01 = __floats2half2_rn(v.x, v.y);
    half2 h23 = __floats2half2_rn(v.z, v.w);
    o.x = *(uint32_t*)&h01;
    o.y = *(uint32_t*)&h23;
    ((uint2*)g_h)[i] = o;
}

// ---------------- pull aggregation from fp16 rows (16B lane loads, 2 nodes/warp) ----------------
// Each half-warp (16 lanes x uint4 = 256 B) owns one node; halves the LDG count
// vs uint2 lanes. Indices fetched 16-at-a-time coalesced, broadcast by width-16
// shuffle with per-half masks (halves stay converged within themselves).
__global__ void aggregate_kernel() {
    int gw = (blockIdx.x * blockDim.x + threadIdx.x) >> 5;
    int lane = threadIdx.x & 31;
    int half_id = lane >> 4;            // 0 or 1
    int sub = lane & 15;                // lane within half-warp
    int n = gw * 2 + half_id;
    if (n >= NN) return;
    unsigned mask = half_id ? 0xFFFF0000u : 0x0000FFFFu;
    int beg = __ldg(&g_off[n]);
    int end = __ldg(&g_off[n + 1]);
    const uint4* h4 = (const uint4*)g_h;   // row = 16 uint4 (256 B)

    float acc[8];
#pragma unroll
    for (int i = 0; i < 8; i++) acc[i] = 0.f;

    for (int cbase = beg; cbase < end; cbase += 16) {
        int m = min(16, end - cbase);
        int idx = (sub < m) ? __ldg(&g_csr[cbase + sub]) : 0;
        int j = 0;
        for (; j + 4 <= m; j += 4) {
            uint4 v[4];
#pragma unroll
            for (int u = 0; u < 4; u++) {
                int s = __shfl_sync(mask, idx, j + u, 16);
                v[u] = __ldg(&h4[(size_t)s * 16 + sub]);
            }
#pragma unroll
            for (int u = 0; u < 4; u++) {
                float2 f0 = __half22float2(*(half2*)&v[u].x);
                float2 f1 = __half22float2(*(half2*)&v[u].y);
                float2 f2 = __half22float2(*(half2*)&v[u].z);
                float2 f3 = __half22float2(*(half2*)&v[u].w);
                acc[0] += f0.x; acc[1] += f0.y;
                acc[2] += f1.x; acc[3] += f1.y;
                acc[4] += f2.x; acc[5] += f2.y;
                acc[6] += f3.x; acc[7] += f3.y;
            }
        }
        for (; j < m; j++) {
            int s = __shfl_sync(mask, idx, j, 16);
            uint4 vv = __ldg(&h4[(size_t)s * 16 + sub]);
            float2 f0 = __half22float2(*(half2*)&vv.x);
            float2 f1 = __half22float2(*(half2*)&vv.y);
            float2 f2 = __half22float2(*(half2*)&vv.z);
            float2 f3 = __half22float2(*(half2*)&vv.w);
            acc[0] += f0.x; acc[1] += f0.y;
            acc[2] += f1.x; acc[3] += f1.y;
            acc[4] += f2.x; acc[5] += f2.y;
            acc[6] += f3.x; acc[7] += f3.y;
        }
    }

    float inv = 1.0f / fmaxf((float)(end - beg), 1.0f);
    float4* outp = (float4*)g_agg + (size_t)n * 32 + sub * 2;
    outp[0] = make_float4(acc[0] * inv, acc[1] * inv, acc[2] * inv, acc[3] * inv);
    outp[1] = make_float4(acc[4] * inv, acc[5] * inv, acc[6] * inv, acc[7] * inv);
}

// ---------------- fp16 hi/lo helpers ----------------
__device__ __forceinline__ uint32_t pack_hi(float a, float b, float& la, float& lb) {
    half ha = __float2half_rn(a);
    half hb = __float2half_rn(b);
    la = a - __half2float(ha);
    lb = b - __half2float(hb);
    half2 h = __halves2half2(ha, hb);     // .x (low) = a
    return *(uint32_t*)&h;
}
__device__ __forceinline__ uint32_t pack_lo(float la, float lb) {
    half2 h = __floats2half2_rn(la, lb);
    return *(uint32_t*)&h;
}

__device__ __forceinline__ void mma_f16(float c[4],
                                        uint32_t a0, uint32_t a1, uint32_t a2, uint32_t a3,
                                        uint32_t b0, uint32_t b1) {
    asm volatile(
        "mma.sync.aligned.m16n8k16.row.col.f32.f16.f16.f32 "
        "{%0,%1,%2,%3}, {%4,%5,%6,%7}, {%8,%9}, {%0,%1,%2,%3};"
        : "+f"(c[0]), "+f"(c[1]), "+f"(c[2]), "+f"(c[3])
        : "r"(a0), "r"(a1), "r"(a2), "r"(a3), "r"(b0), "r"(b1));
}

// ---------------- fused SAGE layer (tensor cores, 3xFP16 hi/lo, m16n8k16) ----------------
#define A_ST 20     // [128][20] uint32 (16 kpairs + 4 pad)
#define B_ST 136    // [16][136] uint32 (128 n + 8 pad)
#define SAGE_SMEM ((2 * 128 * A_ST + 2 * 16 * B_ST + 256 + 128 + 128) * 4)

__global__ void __launch_bounds__(256, 2)
sage_mma_kernel(const float* __restrict__ x_in,
                const float* __restrict__ Wl,
                const float* __restrict__ bl,
                const float* __restrict__ Wr,
                float* __restrict__ x_out,
                int nnodes, int bn_slot, int use_bn) {
    extern __shared__ uint32_t sm[];
    uint32_t* AXhi = sm;                          // [128][A_ST]
    uint32_t* AXlo = AXhi + 128 * A_ST;
    uint32_t* Bhi  = AXlo + 128 * A_ST;           // [16][B_ST]
    uint32_t* Blo  = Bhi + 16 * B_ST;
    float* rowsumS = (float*)(Blo + 16 * B_ST);   // [128][2]
    float* colsumS = rowsumS + 256;               // [128]
    float* colsqS  = colsumS + 128;               // [128]

    const int tid = threadIdx.x;
    const int wid = tid >> 5;
    const int lane = tid & 31;
    const int g = lane >> 2;
    const int t = lane & 3;
    const int warp_m = wid & 3;      // 4 M-warps of 32 rows
    const int warp_n = wid >> 2;     // 2 N-warps of 64 cols
    const int base = blockIdx.x * 128;

    if (tid < 128) { colsumS[tid] = 0.f; colsqS[tid] = 0.f; }

    float c[2][8][4];
#pragma unroll
    for (int mt = 0; mt < 2; mt++)
#pragma unroll
        for (int nt = 0; nt < 8; nt++)
#pragma unroll
            for (int k = 0; k < 4; k++) c[mt][nt][k] = 0.f;

    for (int chunk = 0; chunk < 8; chunk++) {
        const int kBase = chunk * 32;
        const bool isX = (kBase >= 128);
        const bool bnx = isX && use_bn;
        // ---- stage AX chunk: rows 0..127, k kBase..kBase+31, half2-packed along k ----
        const float* srcA = (!isX) ? (g_agg + (size_t)base * DD + kBase)
                                   : (x_in + (size_t)base * DD + (kBase - 128));
#pragma unroll
        for (int i = 0; i < 4; i++) {
            int q = tid + i * 256;          // 0..1023 float4 granules (128 rows x 8 f4)
            int row = q >> 3;
            int f4 = q & 7;
            int grow = base + row;
            float4 v = make_float4(0.f, 0.f, 0.f, 0.f);
            if (grow < nnodes)
                v = __ldg((const float4*)(srcA + (size_t)row * DD) + f4);
            if (bnx) {
                int c4 = ((kBase - 128) >> 2) + f4;
                float4 scv = ((const float4*)g_scale)[c4];
                float4 shv = ((const float4*)g_shift)[c4];
                v.x = fmaxf(fmaf(v.x, scv.x, shv.x), 0.f);
                v.y = fmaxf(fmaf(v.y, scv.y, shv.y), 0.f);
                v.z = fmaxf(fmaf(v.z, scv.z, shv.z), 0.f);
                v.w = fmaxf(fmaf(v.w, scv.w, shv.w), 0.f);
            }
            float lx, ly, lz, lw;
            uint32_t h01 = pack_hi(v.x, v.y, lx, ly);
            uint32_t h23 = pack_hi(v.z, v.w, lz, lw);
            int kp = f4 * 2;
            AXhi[row * A_ST + kp]     = h01;
            AXhi[row * A_ST + kp + 1] = h23;
            AXlo[row * A_ST + kp]     = pack_lo(lx, ly);
            AXlo[row * A_ST + kp + 1] = pack_lo(lz, lw);
        }
        // ---- stage W chunk: rows kBase..+31 of [Wl;Wr], packed (k,k+1) per n ----
        const float* srcW = (!isX) ? (Wl + (size_t)kBase * DD)
                                   : (Wr + (size_t)(kBase - 128) * DD);
#pragma unroll
        for (int i = 0; i < 2; i++) {
            int p = tid + i * 256;          // 0..511 (16 kpairs x 32 n-float4s)
            int kk2 = p >> 5;               // kpair 0..15
            int f4 = p & 31;
            const float* r0 = srcW + (size_t)(2 * kk2) * DD + f4 * 4;
            const float* r1 = r0 + DD;
            float4 va = __ldg((const float4*)r0);
            float4 vb = __ldg((const float4*)r1);
            float l0a, l0b, l1a, l1b, l2a, l2b, l3a, l3b;
            uint32_t h0 = pack_hi(va.x, vb.x, l0a, l0b);   // half2(k, k+1) for n
            uint32_t h1 = pack_hi(va.y, vb.y, l1a, l1b);
            uint32_t h2 = pack_hi(va.z, vb.z, l2a, l2b);
            uint32_t h3 = pack_hi(va.w, vb.w, l3a, l3b);
            uint32_t* ph = Bhi + kk2 * B_ST + f4 * 4;
            uint32_t* pl = Blo + kk2 * B_ST + f4 * 4;
            ph[0] = h0; ph[1] = h1; ph[2] = h2; ph[3] = h3;
            pl[0] = pack_lo(l0a, l0b); pl[1] = pack_lo(l1a, l1b);
            pl[2] = pack_lo(l2a, l2b); pl[3] = pack_lo(l3a, l3b);
        }
        __syncthreads();

        // ---- compute 2 k-steps of 16 ----
#pragma unroll
        for (int ks = 0; ks < 2; ks++) {
            const int kp0 = ks * 8;
            uint32_t ahi[2][4], alo[2][4];
#pragma unroll
            for (int mt = 0; mt < 2; mt++) {
                int r = warp_m * 32 + mt * 16 + g;
                ahi[mt][0] = AXhi[r * A_ST + kp0 + t];
                ahi[mt][1] = AXhi[(r + 8) * A_ST + kp0 + t];
                ahi[mt][2] = AXhi[r * A_ST + kp0 + t + 4];
                ahi[mt][3] = AXhi[(r + 8) * A_ST + kp0 + t + 4];
                alo[mt][0] = AXlo[r * A_ST + kp0 + t];
                alo[mt][1] = AXlo[(r + 8) * A_ST + kp0 + t];
                alo[mt][2] = AXlo[r * A_ST + kp0 + t + 4];
                alo[mt][3] = AXlo[(r + 8) * A_ST + kp0 + t + 4];
            }
#pragma unroll
            for (int nt = 0; nt < 8; nt++) {
                int cn = warp_n * 64 + nt * 8 + g;
                uint32_t bh0 = Bhi[(kp0 + t) * B_ST + cn];
                uint32_t bh1 = Bhi[(kp0 + t + 4) * B_ST + cn];
                uint32_t bl0 = Blo[(kp0 + t) * B_ST + cn];
                uint32_t bl1 = Blo[(kp0 + t + 4) * B_ST + cn];
#pragma unroll
                for (int mt = 0; mt < 2; mt++) {
                    mma_f16(c[mt][nt], ahi[mt][0], ahi[mt][1], ahi[mt][2], ahi[mt][3], bh0, bh1);
                    mma_f16(c[mt][nt], ahi[mt][0], ahi[mt][1], ahi[mt][2], ahi[mt][3], bl0, bl1);
                    mma_f16(c[mt][nt], alo[mt][0], alo[mt][1], alo[mt][2], alo[mt][3], bh0, bh1);
                }
            }
        }
        __syncthreads();
    }

    // ---- epilogue: bias, row L2 norm, store, BN stats ----
#pragma unroll
    for (int nt = 0; nt < 8; nt++) {
        int cn = warp_n * 64 + nt * 8 + 2 * t;
        float b0v = __ldg(&bl[cn]);
        float b1v = __ldg(&bl[cn + 1]);
#pragma unroll
        for (int mt = 0; mt < 2; mt++) {
            c[mt][nt][0] += b0v; c[mt][nt][1] += b1v;
            c[mt][nt][2] += b0v; c[mt][nt][3] += b1v;
        }
    }

#pragma unroll
    for (int mt = 0; mt < 2; mt++) {
        float ssu = 0.f, ssd = 0.f;
#pragma unroll
        for (int nt = 0; nt < 8; nt++) {
            ssu += c[mt][nt][0] * c[mt][nt][0] + c[mt][nt][1] * c[mt][nt][1];
            ssd += c[mt][nt][2] * c[mt][nt][2] + c[mt][nt][3] * c[mt][nt][3];
        }
        ssu += __shfl_xor_sync(0xffffffffu, ssu, 1);
        ssu += __shfl_xor_sync(0xffffffffu, ssu, 2);
        ssd += __shfl_xor_sync(0xffffffffu, ssd, 1);
        ssd += __shfl_xor_sync(0xffffffffu, ssd, 2);
        if (t == 0) {
            int r = warp_m * 32 + mt * 16 + g;
            rowsumS[r * 2 + warp_n] = ssu;
            rowsumS[(r + 8) * 2 + warp_n] = ssd;
        }
    }
    __syncthreads();

    float p1[16], p2[16];
#pragma unroll
    for (int i = 0; i < 16; i++) { p1[i] = 0.f; p2[i] = 0.f; }

#pragma unroll
    for (int mt = 0; mt < 2; mt++) {
        int r_up = warp_m * 32 + mt * 16 + g;
        int r_dn = r_up + 8;
        float su = rowsumS[r_up * 2] + rowsumS[r_up * 2 + 1];
        float sd = rowsumS[r_dn * 2] + rowsumS[r_dn * 2 + 1];
        float invu = 1.0f / fmaxf(sqrtf(su), 1e-12f);
        float invd = 1.0f / fmaxf(sqrtf(sd), 1e-12f);
        int gu = base + r_up, gd = base + r_dn;
        bool vu = gu < nnodes, vd = gd < nnodes;
#pragma unroll
        for (int nt = 0; nt < 8; nt++) {
            int cn = warp_n * 64 + nt * 8 + 2 * t;
            if (vu) {
                float v0 = c[mt][nt][0] * invu, v1 = c[mt][nt][1] * invu;
                *(float2*)(x_out + (size_t)gu * DD + cn) = make_float2(v0, v1);
                p1[nt * 2] += v0; p2[nt * 2] += v0 * v0;
                p1[nt * 2 + 1] += v1; p2[nt * 2 + 1] += v1 * v1;
            }
            if (vd) {
                float v0 = c[mt][nt][2] * invd, v1 = c[mt][nt][3] * invd;
                *(float2*)(x_out + (size_t)gd * DD + cn) = make_float2(v0, v1);
                p1[nt * 2] += v0; p2[nt * 2] += v0 * v0;
                p1[nt * 2 + 1] += v1; p2[nt * 2 + 1] += v1 * v1;
            }
        }
    }

#pragma unroll
    for (int nt = 0; nt < 8; nt++) {
        int cn = warp_n * 64 + nt * 8 + 2 * t;
        atomicAdd(&colsumS[cn], p1[nt * 2]);
        atomicAdd(&colsqS[cn], p2[nt * 2]);
        atomicAdd(&colsumS[cn + 1], p1[nt * 2 + 1]);
        atomicAdd(&colsqS[cn + 1], p2[nt * 2 + 1]);
    }
    __syncthreads();
    if (tid < 128) {
        atomicAdd(&g_bnsum[bn_slot * DD + tid], colsumS[tid]);
        atomicAdd(&g_bnsq[bn_slot * DD + tid], colsqS[tid]);
    }
}

// ---------------- BN params from accumulated sums ----------------
__global__ void bnparams_kernel(const float* __restrict__ g,
                                const float* __restrict__ b,
                                float invN, int bn_slot) {
    int h = threadIdx.x;
    float mean = g_bnsum[bn_slot * DD + h] * invN;
    float var = g_bnsq[bn_slot * DD + h] * invN - mean * mean;
    float sc = g[h] / sqrtf(var + 1e-5f);
    g_scale[h] = sc;
    g_shift[h] = b[h] - mean * sc;
}

// ---------------- per-node dots for the prediction head (applies layer-2 BN+ReLU) ----------------
__global__ void nodedots_kernel(const float* __restrict__ Wlin) {
    int n = (blockIdx.x * blockDim.x + threadIdx.x) >> 5;
    int lane = threadIdx.x & 31;
    if (n >= NN) return;
    float4 a = ((const float4*)g_x2)[(size_t)n * 32 + lane];
    float4 sc = ((const float4*)g_scale)[lane];
    float4 sh = ((const float4*)g_shift)[lane];
    a.x = fmaxf(fmaf(a.x, sc.x, sh.x), 0.f);
    a.y = fmaxf(fmaf(a.y, sc.y, sh.y), 0.f);
    a.z = fmaxf(fmaf(a.z, sc.z, sh.z), 0.f);
    a.w = fmaxf(fmaf(a.w, sc.w, sh.w), 0.f);
    float4 w1 = __ldg(&((const float4*)Wlin)[lane]);
    float4 w2 = __ldg(&((const float4*)Wlin)[32 + lane]);
    float p = a.x * w1.x + a.y * w1.y + a.z * w1.z + a.w * w1.w;
    float q = a.x * w2.x + a.y * w2.y + a.z * w2.z + a.w * w2.w;
#pragma unroll
    for (int m = 16; m; m >>= 1) {
        p += __shfl_xor_sync(0xffffffffu, p, m);
        q += __shfl_xor_sync(0xffffffffu, q, m);
    }
    if (lane == 0) { g_p1[n] = p; g_p2[n] = q; }
}

// ---------------- final prediction: out[e] = p1[s] + p2[d] + blin ----------------
__global__ void predict_kernel(const int* __restrict__ sidx,
                               const int* __restrict__ didx,
                               const float* __restrict__ blin,
                               float* __restrict__ out, int EL) {
    int i = blockIdx.x * blockDim.x + threadIdx.x;
    if (i >= EL) return;
    int s = __ldg(&sidx[i]);
    int d = __ldg(&didx[i]);
    out[i] = g_p1[s] + g_p2[d] + blin[0];
}

// ---------------- launcher ----------------
extern "C" void kernel_launch(void* const* d_in, const int* in_sizes, int n_in,
                              void* d_out, int out_size) {
    const int*   edge_index = (const int*)d_in[0];     // [2, E]
    const int*   elabel     = (const int*)d_in[1];     // [2, EL]
    const float* emb        = (const float*)d_in[2];   // [N, 128]
    const float* Wl1  = (const float*)d_in[3];
    const float* bl1  = (const float*)d_in[4];
    const float* Wr1  = (const float*)d_in[5];
    const float* g1   = (const float*)d_in[6];
    const float* b1   = (const float*)d_in[7];
    const float* Wl2  = (const float*)d_in[8];
    const float* bl2  = (const float*)d_in[9];
    const float* Wr2  = (const float*)d_in[10];
    const float* g2   = (const float*)d_in[11];
    const float* b2   = (const float*)d_in[12];
    const float* Wlin = (const float*)d_in[13];
    const float* blin = (const float*)d_in[14];

    const int E  = in_sizes[0] / 2;
    const int EL = in_sizes[1] / 2;
    const int n  = in_sizes[2] / DD;
    float* out = (float*)d_out;

    cudaFuncSetAttribute(sage_mma_kernel, cudaFuncAttributeMaxDynamicSharedMemorySize, SAGE_SMEM);

    void *p_x1 = nullptr, *p_x2 = nullptr;
    cudaGetSymbolAddress(&p_x1, g_x1);
    cudaGetSymbolAddress(&p_x2, g_x2);
    float* x1 = (float*)p_x1;
    float* x2 = (float*)p_x2;

    const int eblocks = (E + 255) / 256;
    const int gblocks = (n + 127) / 128;
    const int cblocks = (n * (DD / 4) + 255) / 256;  // convert kernels
    const int wblocks = (n + 7) / 8;                 // warp-per-node kernels
    const int a2blocks = (n + 15) / 16;              // 2-nodes-per-warp aggregate
    const float invN = 1.0f / (float)n;

    // ---- CSR build (once; reused by both layers) ----
    init_kernel<<<(NN + 255) / 256, 256>>>();
    hist_kernel<<<eblocks, 256>>>(edge_index + E, E);
    scan1_kernel<<<SCAN_BLOCKS, 1024>>>();
    scan2_kernel<<<1, 128>>>();
    scan3_kernel<<<SCAN_BLOCKS, 1024>>>();
    fill_kernel<<<eblocks, 256>>>(edge_index, edge_index + E, E);

    // ---- layer 1: fp16 copy of emb -> aggregate -> GEMM ----
    tohalf_kernel<false><<<cblocks, 256>>>(emb, n * (DD / 4));
    aggregate_kernel<<<a2blocks, 256>>>();
    sage_mma_kernel<<<gblocks, 256, SAGE_SMEM>>>(emb, Wl1, bl1, Wr1, x1, n, 0, 0);
    bnparams_kernel<<<1, 128>>>(g1, b1, invN, 0);   // -> scale/shift = layer-1 BN

    // ---- layer 2: fp16 copy of relu(bn(x1)) -> aggregate -> GEMM (X-side BN fused fp32) ----
    tohalf_kernel<true><<<cblocks, 256>>>(x1, n * (DD / 4));
    aggregate_kernel<<<a2blocks, 256>>>();
    sage_mma_kernel<<<gblocks, 256, SAGE_SMEM>>>(x1, Wl2, bl2, Wr2, x2, n, 1, 1);
    bnparams_kernel<<<1, 128>>>(g2, b2, invN, 1);   // -> scale/shift = layer-2 BN

    // ---- head (BN+ReLU of x2 fused into nodedots) ----
    nodedots_kernel<<<wblocks, 256>>>(Wlin);
    predict_kernel<<<(EL + 255) / 256, 256>>>(elabel, elabel + EL, blin, out, EL);
}